// round 12
// baseline (speedup 1.0000x reference)
#include <cuda_runtime.h>
#include <cuda_bf16.h>
#include <cstdint>

#define Bsz  8
#define NF   2048
#define NK   4096
#define CIN  256
#define CKQ  64
#define COUT 256
#define SEQ  (NF + NK)

// ---------------- scratch (__device__ globals; no allocations allowed) -----
__device__ __align__(16) __nv_bfloat16 g_Wq[CKQ * CIN];
__device__ __align__(16) __nv_bfloat16 g_Wkv[(CKQ + COUT) * CIN];
__device__ __align__(16) __nv_bfloat16 g_Q[Bsz * NF * CKQ];        // log2-domain scaled
__device__ __align__(16) __nv_bfloat16 g_K[Bsz * NK * CKQ];
__device__ __align__(16) __nv_bfloat16 g_Vt[Bsz * COUT * NK];      // [b][c][key]
__device__ __align__(16) __nv_bfloat16 g_P[Bsz * NF * NK];         // 128 MB, blocked [b][qt][kt][128x128]
__device__ __align__(16) float         g_rsumH[2 * Bsz * NF];      // per-kt-half row sums

// 1/sqrt(64) * log2(e): scores land directly in log2 domain -> ex2.approx
#define SCALE_Q 0.180336884f

// =================== helpers =============================================
__device__ __forceinline__ uint32_t smem_u32(const void* p) {
    uint32_t a;
    asm("{ .reg .u64 t; cvta.to.shared.u64 t, %1; cvt.u32.u64 %0, t; }" : "=r"(a) : "l"(p));
    return a;
}
__device__ __forceinline__ float ex2f(float x) {
    float y; asm("ex2.approx.ftz.f32 %0, %1;" : "=f"(y) : "f"(x)); return y;
}
__device__ __forceinline__ unsigned pack_bf2(float lo, float hi) {
    __nv_bfloat162 h = __floats2bfloat162_rn(lo, hi);
    return *reinterpret_cast<unsigned*>(&h);
}
__device__ __forceinline__ void cp16(uint32_t dst, const void* src) {
    asm volatile("cp.async.cg.shared.global [%0], [%1], 16;" :: "r"(dst), "l"(src) : "memory");
}
#define CP_COMMIT() asm volatile("cp.async.commit_group;" ::: "memory")
#define CP_WAIT(n)  asm volatile("cp.async.wait_group %0;" :: "n"(n) : "memory")

// mma.sync m16n8k16 bf16 -> f32 (sm_80 baseline; family-portable)
__device__ __forceinline__ void mma_bf16(float c[4], const unsigned a[4], const unsigned b[2]) {
    asm volatile(
        "mma.sync.aligned.m16n8k16.row.col.f32.bf16.bf16.f32 "
        "{%0,%1,%2,%3}, {%4,%5,%6,%7}, {%8,%9}, {%0,%1,%2,%3};\n"
        : "+f"(c[0]), "+f"(c[1]), "+f"(c[2]), "+f"(c[3])
        : "r"(a[0]), "r"(a[1]), "r"(a[2]), "r"(a[3]), "r"(b[0]), "r"(b[1]));
}

// ---------------- kernel 0: weight conversion ------------------------------
__global__ void k_convert(const float* __restrict__ Wq, const float* __restrict__ Wk,
                          const float* __restrict__ Wv) {
    int i = blockIdx.x * blockDim.x + threadIdx.x;
    const int n1 = CKQ * CIN;
    const int n2 = (CKQ + COUT) * CIN;
    if (i < n1) g_Wq[i] = __float2bfloat16_rn(Wq[i]);
    if (i < n2) g_Wkv[i] = __float2bfloat16_rn(i < n1 ? Wk[i] : Wv[i - n1]);
}

// ---------------- kernel 1: fused QKV projection + keep-row copy -----------
// 128-row tile per CTA (grid 384, 84.5KB smem -> 2 CTAs/SM), 8 warps x M16.
#define AS_STRIDE 264
#define VS_STRIDE 66
#define PROJ_SMEM (128 * AS_STRIDE * 2 + 128 * VS_STRIDE * 2)   // 84480

__global__ __launch_bounds__(256) void k_proj(const float* __restrict__ feat,
                                              const float* __restrict__ bq,
                                              const float* __restrict__ bk,
                                              const float* __restrict__ bv,
                                              float* __restrict__ out) {
    extern __shared__ char smem[];
    __nv_bfloat16* As  = reinterpret_cast<__nv_bfloat16*>(smem);
    __nv_bfloat16* Vsm = reinterpret_cast<__nv_bfloat16*>(smem + 128 * AS_STRIDE * 2);

    const int tid = threadIdx.x;
    const int w = tid >> 5, lane = tid & 31;
    const int g = lane >> 2, t = lane & 3;
    const int m0 = w * 16;

    const int row0 = blockIdx.x * 128;
    const int b = row0 / SEQ;
    const int pos0 = row0 % SEQ;
    const bool is_fill = pos0 < NF;

    // exact fp32 pass-through of keep rows
    if (!is_fill) {
        const float4* src = reinterpret_cast<const float4*>(feat + (size_t)row0 * CIN);
        float4* dst = reinterpret_cast<float4*>(out + (size_t)row0 * CIN);
        for (int i = tid; i < 128 * CIN / 4; i += 256) dst[i] = src[i];
    }

    // stage feature tile (128 x 256) as bf16 in smem
    for (int i = tid; i < 128 * 64; i += 256) {
        const int r = i >> 6, c4 = i & 63;
        float4 v = *reinterpret_cast<const float4*>(&feat[(size_t)(row0 + r) * CIN + c4 * 4]);
        *reinterpret_cast<__nv_bfloat162*>(&As[r * AS_STRIDE + c4 * 4]) = __floats2bfloat162_rn(v.x, v.y);
        *reinterpret_cast<__nv_bfloat162*>(&As[r * AS_STRIDE + c4 * 4 + 2]) = __floats2bfloat162_rn(v.z, v.w);
    }
    __syncthreads();

    const int nchunks = is_fill ? 1 : 5;   // fill: Q(64). keep: K(64) + 4x V(64)
    for (int nc = 0; nc < nchunks; nc++) {
        const __nv_bfloat16* W = is_fill ? g_Wq : g_Wkv;
        const int nbase = is_fill ? 0 : nc * 64;

        float acc[8][4];
#pragma unroll
        for (int nt = 0; nt < 8; nt++) { acc[nt][0] = acc[nt][1] = acc[nt][2] = acc[nt][3] = 0.f; }

#pragma unroll
        for (int kt = 0; kt < 16; kt++) {
            const int k0 = kt * 16;
            unsigned a[4];
            a[0] = *reinterpret_cast<const unsigned*>(&As[(m0 + g)     * AS_STRIDE + k0 + 2 * t]);
            a[1] = *reinterpret_cast<const unsigned*>(&As[(m0 + g + 8) * AS_STRIDE + k0 + 2 * t]);
            a[2] = *reinterpret_cast<const unsigned*>(&As[(m0 + g)     * AS_STRIDE + k0 + 8 + 2 * t]);
            a[3] = *reinterpret_cast<const unsigned*>(&As[(m0 + g + 8) * AS_STRIDE + k0 + 8 + 2 * t]);
#pragma unroll
            for (int nt = 0; nt < 8; nt++) {
                const int n = nbase + nt * 8 + g;
                unsigned bf[2];
                bf[0] = *reinterpret_cast<const unsigned*>(&W[n * CIN + k0 + 2 * t]);
                bf[1] = *reinterpret_cast<const unsigned*>(&W[n * CIN + k0 + 8 + 2 * t]);
                mma_bf16(acc[nt], a, bf);
            }
        }

        if (is_fill) {
            const int qrow = b * NF + pos0 + m0 + g;
#pragma unroll
            for (int nt = 0; nt < 8; nt++) {
                const int col = nt * 8 + 2 * t;
                const float b0v = bq[col], b1v = bq[col + 1];
                *reinterpret_cast<unsigned*>(&g_Q[(size_t)qrow * CKQ + col]) =
                    pack_bf2((acc[nt][0] + b0v) * SCALE_Q, (acc[nt][1] + b1v) * SCALE_Q);
                *reinterpret_cast<unsigned*>(&g_Q[(size_t)(qrow + 8) * CKQ + col]) =
                    pack_bf2((acc[nt][2] + b0v) * SCALE_Q, (acc[nt][3] + b1v) * SCALE_Q);
            }
        } else if (nc == 0) {
            const int krow = b * NK + (pos0 - NF) + m0 + g;
#pragma unroll
            for (int nt = 0; nt < 8; nt++) {
                const int col = nt * 8 + 2 * t;
                const float b0v = bk[col], b1v = bk[col + 1];
                *reinterpret_cast<unsigned*>(&g_K[(size_t)krow * CKQ + col]) =
                    pack_bf2(acc[nt][0] + b0v, acc[nt][1] + b1v);
                *reinterpret_cast<unsigned*>(&g_K[(size_t)(krow + 8) * CKQ + col]) =
                    pack_bf2(acc[nt][2] + b0v, acc[nt][3] + b1v);
            }
        } else {
            // V chunk -> smem -> transposed global write ([c][key])
#pragma unroll
            for (int nt = 0; nt < 8; nt++) {
                const int col = nt * 8 + 2 * t;
                const int nglob = (nc - 1) * 64 + col;
                const float b0v = bv[nglob], b1v = bv[nglob + 1];
                *reinterpret_cast<unsigned*>(&Vsm[(m0 + g)     * VS_STRIDE + col]) =
                    pack_bf2(acc[nt][0] + b0v, acc[nt][1] + b1v);
                *reinterpret_cast<unsigned*>(&Vsm[(m0 + g + 8) * VS_STRIDE + col]) =
                    pack_bf2(acc[nt][2] + b0v, acc[nt][3] + b1v);
            }
            __syncthreads();
            const int key0 = pos0 - NF;
            for (int i = tid; i < 64 * 64; i += 256) {
                const int n = i >> 6;
                const int kp = i & 63;
                __nv_bfloat162 h;
                h.x = Vsm[(2 * kp)     * VS_STRIDE + n];
                h.y = Vsm[(2 * kp + 1) * VS_STRIDE + n];
                const int nglob = (nc - 1) * 64 + n;
                *reinterpret_cast<__nv_bfloat162*>(
                    &g_Vt[((size_t)(b * COUT + nglob)) * NK + key0 + 2 * kp]) = h;
            }
            __syncthreads();
        }
    }
}

// ---------------- kernel 2: scores + exp -> unnormalized P -----------------
// Each CTA: 128 q rows x HALF the KV range (16 tiles). grid = 8*16*2 = 256.
// 8 warps x M16, 3-stage cp.async K pipeline. Partial row sums -> g_rsumH.
#define SC_QS 72
#define SC_KS 72
#define SC_SMK(s) (18432 + (s) * 18432)
#define SCORE_SMEM (4 * 18432)     // Q + 3 K stages = 73728

__global__ __launch_bounds__(256, 1) void k_score() {
    extern __shared__ char smem[];
    const uint32_t sb = smem_u32(smem);
    const int tid = threadIdx.x;
    const int w = tid >> 5, lane = tid & 31;
    const int g = lane >> 2, t = lane & 3;
    const int m0 = w * 16;
    const int b  = blockIdx.x >> 5;
    const int qt = (blockIdx.x >> 1) & 15;
    const int h  = blockIdx.x & 1;
    const int q0 = qt * 128;
    const int kt0 = h * 16;

    const __nv_bfloat16* gK = &g_K[(size_t)(b * NK) * CKQ];

    // stage Q tile
    for (int i = tid; i < 128 * 8; i += 256) {
        const int r = i >> 3, c4 = i & 7;
        const uint4 v = *reinterpret_cast<const uint4*>(
            &g_Q[((size_t)(b * NF + q0 + r)) * CKQ + c4 * 8]);
        *reinterpret_cast<uint4*>(smem + (r * SC_QS + c4 * 8) * 2) = v;
    }

    // prefetch K tiles kt0 .. kt0+2
#pragma unroll
    for (int pre = 0; pre < 3; pre++) {
        const uint32_t kb = sb + SC_SMK(pre);
        for (int i = tid; i < 1024; i += 256) {
            const int r = i >> 3, c = i & 7;
            cp16(kb + (r * SC_KS + c * 8) * 2, gK + (size_t)((kt0 + pre) * 128 + r) * CKQ + c * 8);
        }
        CP_COMMIT();
    }
    __syncthreads();

    const __nv_bfloat16* Qs = reinterpret_cast<const __nv_bfloat16*>(smem);
    unsigned qf[4][4];
#pragma unroll
    for (int j = 0; j < 4; j++) {
        const int k0 = j * 16;
        qf[j][0] = *reinterpret_cast<const unsigned*>(&Qs[(m0 + g)     * SC_QS + k0 + 2 * t]);
        qf[j][1] = *reinterpret_cast<const unsigned*>(&Qs[(m0 + g + 8) * SC_QS + k0 + 2 * t]);
        qf[j][2] = *reinterpret_cast<const unsigned*>(&Qs[(m0 + g)     * SC_QS + k0 + 8 + 2 * t]);
        qf[j][3] = *reinterpret_cast<const unsigned*>(&Qs[(m0 + g + 8) * SC_QS + k0 + 8 + 2 * t]);
    }

    float rsum0 = 0.f, rsum1 = 0.f;
    uint32_t* pbase = reinterpret_cast<uint32_t*>(&g_P[((size_t)(b * 16 + qt)) * 32 * 16384]);

    for (int i = 0; i < 16; i++) {
        const int kt = kt0 + i;
        const int s = i % 3;
        const __nv_bfloat16* Ks = reinterpret_cast<const __nv_bfloat16*>(smem + SC_SMK(s));

        CP_WAIT(2);
        __syncthreads();

        float sv[16][4];
#pragma unroll
        for (int nt = 0; nt < 16; nt++) { sv[nt][0] = sv[nt][1] = sv[nt][2] = sv[nt][3] = 0.f; }
#pragma unroll
        for (int j = 0; j < 4; j++) {
            const int k0 = j * 16;
#pragma unroll
            for (int nt = 0; nt < 16; nt++) {
                const int n = nt * 8 + g;
                unsigned bf[2];
                bf[0] = *reinterpret_cast<const unsigned*>(&Ks[n * SC_KS + k0 + 2 * t]);
                bf[1] = *reinterpret_cast<const unsigned*>(&Ks[n * SC_KS + k0 + 8 + 2 * t]);
                mma_bf16(sv[nt], qf[j], bf);
            }
        }

        __syncthreads();                    // done reading stage s
        if (i + 3 < 16) {                   // prefetch tile kt+3 into stage s
            const uint32_t kb = sb + SC_SMK(s);
            for (int ii = tid; ii < 1024; ii += 256) {
                const int r = ii >> 3, c = ii & 7;
                cp16(kb + (r * SC_KS + c * 8) * 2, gK + (size_t)((kt + 3) * 128 + r) * CKQ + c * 8);
            }
        }
        CP_COMMIT();                        // always: keeps wait_group accounting exact

        // exp (log2 domain), partial row sums, pack + store unnormalized P
        uint32_t* pb = pbase + kt * 8192;
#pragma unroll
        for (int nt = 0; nt < 16; nt++) {
            const float p0 = ex2f(sv[nt][0]);
            const float p1 = ex2f(sv[nt][1]);
            const float p2 = ex2f(sv[nt][2]);
            const float p3 = ex2f(sv[nt][3]);
            rsum0 += p0 + p1;
            rsum1 += p2 + p3;
            pb[(m0 + g) * 64     + nt * 4 + t] = pack_bf2(p0, p1);
            pb[(m0 + g + 8) * 64 + nt * 4 + t] = pack_bf2(p2, p3);
        }
    }

    // quad-reduce partial row sums, lane t==0 writes this half's sums
    rsum0 += __shfl_xor_sync(0xffffffffu, rsum0, 1);
    rsum0 += __shfl_xor_sync(0xffffffffu, rsum0, 2);
    rsum1 += __shfl_xor_sync(0xffffffffu, rsum1, 1);
    rsum1 += __shfl_xor_sync(0xffffffffu, rsum1, 2);
    if (t == 0) {
        g_rsumH[h * (Bsz * NF) + b * NF + q0 + m0 + g]     = rsum0;
        g_rsumH[h * (Bsz * NF) + b * NF + q0 + m0 + g + 8] = rsum1;
    }
}

// ---------------- kernel 3: O = P @ V, scaled by 1/rsum --------------------
// CTA: 128 q x 128 out channels, 512 threads, 16 warps (4M x 4N), M32N32/warp.
// 2-stage cp.async: A = P block 32KB, B = Vt slice 32KB per stage.
#define PV_ST 136                         // halves stride (128 + 8)
#define PV_STAGE 69632                    // 34816 (A) + 34816 (B)
#define PV_SMEM (2 * PV_STAGE)            // 139264

__global__ __launch_bounds__(512, 1) void k_pv(float* __restrict__ out) {
    extern __shared__ char smem[];
    const uint32_t sb = smem_u32(smem);
    const int tid = threadIdx.x;
    const int w = tid >> 5, lane = tid & 31;
    const int g = lane >> 2, t = lane & 3;
    const int mw = w & 3, nw = w >> 2;          // 4 x 4 warp grid
    const int mbase = mw * 32, nbase = nw * 32;

    const int b  = blockIdx.x >> 5;
    const int qt = (blockIdx.x >> 1) & 15;
    const int nh = blockIdx.x & 1;
    const int q0 = qt * 128;

    const __nv_bfloat16* gP = &g_P[((size_t)(b * 16 + qt)) * 32 * 16384];
    const __nv_bfloat16* gV = &g_Vt[((size_t)(b * COUT + nh * 128)) * NK];

    // prefetch kt = 0, 1
#pragma unroll
    for (int pre = 0; pre < 2; pre++) {
        const uint32_t ab = sb + pre * PV_STAGE;
        const uint32_t bb = ab + 34816;
        for (int i = tid; i < 2048; i += 512) {
            const int r = i >> 4, c = i & 15;
            cp16(ab + r * (PV_ST * 2) + c * 16, gP + (size_t)pre * 16384 + r * 128 + c * 8);
            cp16(bb + r * (PV_ST * 2) + c * 16, gV + (size_t)r * NK + pre * 128 + c * 8);
        }
        CP_COMMIT();
    }

    float acc[2][4][4];
#pragma unroll
    for (int mt = 0; mt < 2; mt++)
#pragma unroll
        for (int nt = 0; nt < 4; nt++) {
            acc[mt][nt][0] = acc[mt][nt][1] = acc[mt][nt][2] = acc[mt][nt][3] = 0.f;
        }

    for (int kt = 0; kt < 32; kt++) {
        const int s = kt & 1;
        const __nv_bfloat16* As_ = reinterpret_cast<const __nv_bfloat16*>(smem + s * PV_STAGE);
        const __nv_bfloat16* Bs_ = As_ + 17408;   // 34816 bytes / 2

        CP_WAIT(1);
        __syncthreads();

#pragma unroll
        for (int kk = 0; kk < 8; kk++) {
            const int k0 = kk * 16;
            unsigned a[2][4];
#pragma unroll
            for (int mt = 0; mt < 2; mt++) {
                const int r0 = mbase + mt * 16 + g;
                a[mt][0] = *reinterpret_cast<const unsigned*>(&As_[r0       * PV_ST + k0 + 2 * t]);
                a[mt][1] = *reinterpret_cast<const unsigned*>(&As_[(r0 + 8) * PV_ST + k0 + 2 * t]);
                a[mt][2] = *reinterpret_cast<const unsigned*>(&As_[r0       * PV_ST + k0 + 8 + 2 * t]);
                a[mt][3] = *reinterpret_cast<const unsigned*>(&As_[(r0 + 8) * PV_ST + k0 + 8 + 2 * t]);
            }
#pragma unroll
            for (int nt = 0; nt < 4; nt++) {
                const int n = nbase + nt * 8 + g;
                unsigned bf[2];
                bf[0] = *reinterpret_cast<const unsigned*>(&Bs_[n * PV_ST + k0 + 2 * t]);
                bf[1] = *reinterpret_cast<const unsigned*>(&Bs_[n * PV_ST + k0 + 8 + 2 * t]);
                mma_bf16(acc[0][nt], a[0], bf);
                mma_bf16(acc[1][nt], a[1], bf);
            }
        }

        __syncthreads();
        if (kt + 2 < 32) {
            const uint32_t ab = sb + s * PV_STAGE;
            const uint32_t bb = ab + 34816;
            const int tn = kt + 2;
            for (int i = tid; i < 2048; i += 512) {
                const int r = i >> 4, c = i & 15;
                cp16(ab + r * (PV_ST * 2) + c * 16, gP + (size_t)tn * 16384 + r * 128 + c * 8);
                cp16(bb + r * (PV_ST * 2) + c * 16, gV + (size_t)r * NK + tn * 128 + c * 8);
            }
        }
        CP_COMMIT();
    }

    // epilogue: scale by 1/(rsum half0 + half1), write fp32 output
#pragma unroll
    for (int mt = 0; mt < 2; mt++) {
        const int r = mbase + mt * 16 + g;
        const int ridx = b * NF + q0 + r;
        const float ia = 1.f / (g_rsumH[ridx]     + g_rsumH[Bsz * NF + ridx]);
        const float ib = 1.f / (g_rsumH[ridx + 8] + g_rsumH[Bsz * NF + ridx + 8]);
        const size_t row0 = (size_t)(b * SEQ + q0 + r) * COUT;
        const size_t row1 = (size_t)(b * SEQ + q0 + r + 8) * COUT;
#pragma unroll
        for (int nt = 0; nt < 4; nt++) {
            const int col = nh * 128 + nbase + nt * 8 + 2 * t;
            *reinterpret_cast<float2*>(&out[row0 + col]) =
                make_float2(acc[mt][nt][0] * ia, acc[mt][nt][1] * ia);
            *reinterpret_cast<float2*>(&out[row1 + col]) =
                make_float2(acc[mt][nt][2] * ib, acc[mt][nt][3] * ib);
        }
    }
}

// ---------------- launch ----------------------------------------------------
extern "C" void kernel_launch(void* const* d_in, const int* in_sizes, int n_in,
                              void* d_out, int out_size) {
    const float* feat = (const float*)d_in[0];
    // d_in[1] = keep_flag (unused; layout is deterministic)
    const float* Wq = (const float*)d_in[2];
    const float* bq = (const float*)d_in[3];
    const float* Wk = (const float*)d_in[4];
    const float* bk = (const float*)d_in[5];
    const float* Wv = (const float*)d_in[6];
    const float* bv = (const float*)d_in[7];
    float* out = (float*)d_out;

    cudaFuncSetAttribute(k_proj,  cudaFuncAttributeMaxDynamicSharedMemorySize, PROJ_SMEM);
    cudaFuncSetAttribute(k_score, cudaFuncAttributeMaxDynamicSharedMemorySize, SCORE_SMEM);
    cudaFuncSetAttribute(k_pv,    cudaFuncAttributeMaxDynamicSharedMemorySize, PV_SMEM);

    k_convert<<<320, 256>>>(Wq, Wk, Wv);
    k_proj<<<(Bsz * SEQ) / 128, 256, PROJ_SMEM>>>(feat, bq, bk, bv, out);
    k_score<<<Bsz * 16 * 2, 256, SCORE_SMEM>>>();
    k_pv<<<Bsz * 16 * 2, 512, PV_SMEM>>>(out);
}

// round 13
// speedup vs baseline: 1.1834x; 1.1834x over previous
#include <cuda_runtime.h>
#include <cuda_bf16.h>
#include <cstdint>

#define Bsz  8
#define NF   2048
#define NK   4096
#define CIN  256
#define CKQ  64
#define COUT 256
#define SEQ  (NF + NK)

// ---------------- scratch (__device__ globals; no allocations allowed) -----
__device__ __align__(16) __nv_bfloat16 g_Wq[CKQ * CIN];
__device__ __align__(16) __nv_bfloat16 g_Wkv[(CKQ + COUT) * CIN];
__device__ __align__(16) __nv_bfloat16 g_Q[Bsz * NF * CKQ];        // log2-domain scaled
__device__ __align__(16) __nv_bfloat16 g_K[Bsz * NK * CKQ];
__device__ __align__(16) __nv_bfloat16 g_Vt[Bsz * COUT * NK];      // [b][c][key]
__device__ __align__(16) __nv_bfloat16 g_P[Bsz * NF * NK];         // 128 MB, blocked [b][qt][kt][128x128]
__device__ __align__(16) float         g_rsumH[2 * Bsz * NF];      // per-kt-half row sums

// 1/sqrt(64) * log2(e): scores land directly in log2 domain -> ex2.approx
#define SCALE_Q 0.180336884f

// =================== helpers =============================================
__device__ __forceinline__ uint32_t smem_u32(const void* p) {
    uint32_t a;
    asm("{ .reg .u64 t; cvta.to.shared.u64 t, %1; cvt.u32.u64 %0, t; }" : "=r"(a) : "l"(p));
    return a;
}
__device__ __forceinline__ float ex2f(float x) {
    float y; asm("ex2.approx.ftz.f32 %0, %1;" : "=f"(y) : "f"(x)); return y;
}
__device__ __forceinline__ unsigned pack_bf2(float lo, float hi) {
    __nv_bfloat162 h = __floats2bfloat162_rn(lo, hi);
    return *reinterpret_cast<unsigned*>(&h);
}
__device__ __forceinline__ void cp16(uint32_t dst, const void* src) {
    asm volatile("cp.async.cg.shared.global [%0], [%1], 16;" :: "r"(dst), "l"(src) : "memory");
}
#define CP_COMMIT() asm volatile("cp.async.commit_group;" ::: "memory")
#define CP_WAIT(n)  asm volatile("cp.async.wait_group %0;" :: "n"(n) : "memory")

// mma.sync m16n8k16 bf16 -> f32 (sm_80 baseline; family-portable)
__device__ __forceinline__ void mma_bf16(float c[4], const unsigned a[4], const unsigned b[2]) {
    asm volatile(
        "mma.sync.aligned.m16n8k16.row.col.f32.bf16.bf16.f32 "
        "{%0,%1,%2,%3}, {%4,%5,%6,%7}, {%8,%9}, {%0,%1,%2,%3};\n"
        : "+f"(c[0]), "+f"(c[1]), "+f"(c[2]), "+f"(c[3])
        : "r"(a[0]), "r"(a[1]), "r"(a[2]), "r"(a[3]), "r"(b[0]), "r"(b[1]));
}

// ---------------- kernel 0: weight conversion ------------------------------
__global__ void k_convert(const float* __restrict__ Wq, const float* __restrict__ Wk,
                          const float* __restrict__ Wv) {
    int i = blockIdx.x * blockDim.x + threadIdx.x;
    const int n1 = CKQ * CIN;
    const int n2 = (CKQ + COUT) * CIN;
    if (i < n1) g_Wq[i] = __float2bfloat16_rn(Wq[i]);
    if (i < n2) g_Wkv[i] = __float2bfloat16_rn(i < n1 ? Wk[i] : Wv[i - n1]);
}

// ---------------- kernel 1: fused QKV projection + keep-row copy -----------
// 256-row tile per CTA, 8 warps x M32 (R10 best-known config).
#define AS_STRIDE 264
#define VS_STRIDE 66
#define PROJ_SMEM (256 * AS_STRIDE * 2 + 256 * VS_STRIDE * 2)   // 168960

__global__ __launch_bounds__(256) void k_proj(const float* __restrict__ feat,
                                              const float* __restrict__ bq,
                                              const float* __restrict__ bk,
                                              const float* __restrict__ bv,
                                              float* __restrict__ out) {
    extern __shared__ char smem[];
    __nv_bfloat16* As  = reinterpret_cast<__nv_bfloat16*>(smem);
    __nv_bfloat16* Vsm = reinterpret_cast<__nv_bfloat16*>(smem + 256 * AS_STRIDE * 2);

    const int tid = threadIdx.x;
    const int w = tid >> 5, lane = tid & 31;
    const int g = lane >> 2, t = lane & 3;
    const int m0 = w * 32;

    const int row0 = blockIdx.x * 256;
    const int b = row0 / SEQ;
    const int pos0 = row0 % SEQ;
    const bool is_fill = pos0 < NF;

    if (!is_fill) {
        const float4* src = reinterpret_cast<const float4*>(feat + (size_t)row0 * CIN);
        float4* dst = reinterpret_cast<float4*>(out + (size_t)row0 * CIN);
        for (int i = tid; i < 256 * CIN / 4; i += 256) dst[i] = src[i];
    }

    for (int i = tid; i < 256 * 64; i += 256) {
        const int r = i >> 6, c4 = i & 63;
        float4 v = *reinterpret_cast<const float4*>(&feat[(size_t)(row0 + r) * CIN + c4 * 4]);
        *reinterpret_cast<__nv_bfloat162*>(&As[r * AS_STRIDE + c4 * 4]) = __floats2bfloat162_rn(v.x, v.y);
        *reinterpret_cast<__nv_bfloat162*>(&As[r * AS_STRIDE + c4 * 4 + 2]) = __floats2bfloat162_rn(v.z, v.w);
    }
    __syncthreads();

    const int nchunks = is_fill ? 1 : 5;
    for (int nc = 0; nc < nchunks; nc++) {
        const __nv_bfloat16* W = is_fill ? g_Wq : g_Wkv;
        const int nbase = is_fill ? 0 : nc * 64;

        float acc[2][8][4];
#pragma unroll
        for (int mt = 0; mt < 2; mt++)
#pragma unroll
            for (int nt = 0; nt < 8; nt++) {
                acc[mt][nt][0] = acc[mt][nt][1] = acc[mt][nt][2] = acc[mt][nt][3] = 0.f;
            }

#pragma unroll
        for (int kt = 0; kt < 16; kt++) {
            const int k0 = kt * 16;
            unsigned a[2][4];
#pragma unroll
            for (int mt = 0; mt < 2; mt++) {
                const int r0 = m0 + mt * 16 + g;
                a[mt][0] = *reinterpret_cast<const unsigned*>(&As[r0       * AS_STRIDE + k0 + 2 * t]);
                a[mt][1] = *reinterpret_cast<const unsigned*>(&As[(r0 + 8) * AS_STRIDE + k0 + 2 * t]);
                a[mt][2] = *reinterpret_cast<const unsigned*>(&As[r0       * AS_STRIDE + k0 + 8 + 2 * t]);
                a[mt][3] = *reinterpret_cast<const unsigned*>(&As[(r0 + 8) * AS_STRIDE + k0 + 8 + 2 * t]);
            }
#pragma unroll
            for (int nt = 0; nt < 8; nt++) {
                const int n = nbase + nt * 8 + g;
                unsigned bf[2];
                bf[0] = *reinterpret_cast<const unsigned*>(&W[n * CIN + k0 + 2 * t]);
                bf[1] = *reinterpret_cast<const unsigned*>(&W[n * CIN + k0 + 8 + 2 * t]);
                mma_bf16(acc[0][nt], a[0], bf);
                mma_bf16(acc[1][nt], a[1], bf);
            }
        }

        if (is_fill) {
#pragma unroll
            for (int mt = 0; mt < 2; mt++) {
                const int qrow = b * NF + pos0 + m0 + mt * 16 + g;
#pragma unroll
                for (int nt = 0; nt < 8; nt++) {
                    const int col = nt * 8 + 2 * t;
                    const float b0v = bq[col], b1v = bq[col + 1];
                    *reinterpret_cast<unsigned*>(&g_Q[(size_t)qrow * CKQ + col]) =
                        pack_bf2((acc[mt][nt][0] + b0v) * SCALE_Q, (acc[mt][nt][1] + b1v) * SCALE_Q);
                    *reinterpret_cast<unsigned*>(&g_Q[(size_t)(qrow + 8) * CKQ + col]) =
                        pack_bf2((acc[mt][nt][2] + b0v) * SCALE_Q, (acc[mt][nt][3] + b1v) * SCALE_Q);
                }
            }
        } else if (nc == 0) {
#pragma unroll
            for (int mt = 0; mt < 2; mt++) {
                const int krow = b * NK + (pos0 - NF) + m0 + mt * 16 + g;
#pragma unroll
                for (int nt = 0; nt < 8; nt++) {
                    const int col = nt * 8 + 2 * t;
                    const float b0v = bk[col], b1v = bk[col + 1];
                    *reinterpret_cast<unsigned*>(&g_K[(size_t)krow * CKQ + col]) =
                        pack_bf2(acc[mt][nt][0] + b0v, acc[mt][nt][1] + b1v);
                    *reinterpret_cast<unsigned*>(&g_K[(size_t)(krow + 8) * CKQ + col]) =
                        pack_bf2(acc[mt][nt][2] + b0v, acc[mt][nt][3] + b1v);
                }
            }
        } else {
#pragma unroll
            for (int mt = 0; mt < 2; mt++) {
                const int r0 = m0 + mt * 16 + g;
#pragma unroll
                for (int nt = 0; nt < 8; nt++) {
                    const int col = nt * 8 + 2 * t;
                    const int nglob = (nc - 1) * 64 + col;
                    const float b0v = bv[nglob], b1v = bv[nglob + 1];
                    *reinterpret_cast<unsigned*>(&Vsm[r0       * VS_STRIDE + col]) =
                        pack_bf2(acc[mt][nt][0] + b0v, acc[mt][nt][1] + b1v);
                    *reinterpret_cast<unsigned*>(&Vsm[(r0 + 8) * VS_STRIDE + col]) =
                        pack_bf2(acc[mt][nt][2] + b0v, acc[mt][nt][3] + b1v);
                }
            }
            __syncthreads();
            const int key0 = pos0 - NF;
            for (int i = tid; i < 64 * 128; i += 256) {
                const int n = i >> 7;
                const int kp = i & 127;
                __nv_bfloat162 h;
                h.x = Vsm[(2 * kp)     * VS_STRIDE + n];
                h.y = Vsm[(2 * kp + 1) * VS_STRIDE + n];
                const int nglob = (nc - 1) * 64 + n;
                *reinterpret_cast<__nv_bfloat162*>(
                    &g_Vt[((size_t)(b * COUT + nglob)) * NK + key0 + 2 * kp]) = h;
            }
            __syncthreads();
        }
    }
}

// ---------------- kernel 2: scores + exp -> unnormalized P -----------------
// Each CTA: 128 q rows x HALF the KV range (16 tiles). grid = 8*16*2 = 256.
// Reg-capped to 128 -> 2 CTAs/SM co-residency. 3-stage cp.async K pipeline.
#define SC_QS 72
#define SC_KS 72
#define SC_SMK(s) (18432 + (s) * 18432)
#define SCORE_SMEM (4 * 18432)     // Q + 3 K stages = 73728

__global__ __launch_bounds__(256, 2) void k_score() {
    extern __shared__ char smem[];
    const uint32_t sb = smem_u32(smem);
    const int tid = threadIdx.x;
    const int w = tid >> 5, lane = tid & 31;
    const int g = lane >> 2, t = lane & 3;
    const int m0 = w * 16;
    const int b  = blockIdx.x >> 5;
    const int qt = (blockIdx.x >> 1) & 15;
    const int h  = blockIdx.x & 1;
    const int q0 = qt * 128;
    const int kt0 = h * 16;

    const __nv_bfloat16* gK = &g_K[(size_t)(b * NK) * CKQ];

    // stage Q tile
    for (int i = tid; i < 128 * 8; i += 256) {
        const int r = i >> 3, c4 = i & 7;
        const uint4 v = *reinterpret_cast<const uint4*>(
            &g_Q[((size_t)(b * NF + q0 + r)) * CKQ + c4 * 8]);
        *reinterpret_cast<uint4*>(smem + (r * SC_QS + c4 * 8) * 2) = v;
    }

    // prefetch K tiles kt0 .. kt0+2
#pragma unroll
    for (int pre = 0; pre < 3; pre++) {
        const uint32_t kb = sb + SC_SMK(pre);
        for (int i = tid; i < 1024; i += 256) {
            const int r = i >> 3, c = i & 7;
            cp16(kb + (r * SC_KS + c * 8) * 2, gK + (size_t)((kt0 + pre) * 128 + r) * CKQ + c * 8);
        }
        CP_COMMIT();
    }
    __syncthreads();

    const __nv_bfloat16* Qs = reinterpret_cast<const __nv_bfloat16*>(smem);
    unsigned qf[4][4];
#pragma unroll
    for (int j = 0; j < 4; j++) {
        const int k0 = j * 16;
        qf[j][0] = *reinterpret_cast<const unsigned*>(&Qs[(m0 + g)     * SC_QS + k0 + 2 * t]);
        qf[j][1] = *reinterpret_cast<const unsigned*>(&Qs[(m0 + g + 8) * SC_QS + k0 + 2 * t]);
        qf[j][2] = *reinterpret_cast<const unsigned*>(&Qs[(m0 + g)     * SC_QS + k0 + 8 + 2 * t]);
        qf[j][3] = *reinterpret_cast<const unsigned*>(&Qs[(m0 + g + 8) * SC_QS + k0 + 8 + 2 * t]);
    }

    float rsum0 = 0.f, rsum1 = 0.f;
    uint32_t* pbase = reinterpret_cast<uint32_t*>(&g_P[((size_t)(b * 16 + qt)) * 32 * 16384]);

    for (int i = 0; i < 16; i++) {
        const int kt = kt0 + i;
        const int s = i % 3;
        const __nv_bfloat16* Ks = reinterpret_cast<const __nv_bfloat16*>(smem + SC_SMK(s));

        CP_WAIT(2);
        __syncthreads();

        float sv[16][4];
#pragma unroll
        for (int nt = 0; nt < 16; nt++) { sv[nt][0] = sv[nt][1] = sv[nt][2] = sv[nt][3] = 0.f; }
#pragma unroll
        for (int j = 0; j < 4; j++) {
            const int k0 = j * 16;
#pragma unroll
            for (int nt = 0; nt < 16; nt++) {
                const int n = nt * 8 + g;
                unsigned bf[2];
                bf[0] = *reinterpret_cast<const unsigned*>(&Ks[n * SC_KS + k0 + 2 * t]);
                bf[1] = *reinterpret_cast<const unsigned*>(&Ks[n * SC_KS + k0 + 8 + 2 * t]);
                mma_bf16(sv[nt], qf[j], bf);
            }
        }

        __syncthreads();                    // done reading stage s
        if (i + 3 < 16) {                   // prefetch tile kt+3 into stage s
            const uint32_t kb = sb + SC_SMK(s);
            for (int ii = tid; ii < 1024; ii += 256) {
                const int r = ii >> 3, c = ii & 7;
                cp16(kb + (r * SC_KS + c * 8) * 2, gK + (size_t)((kt + 3) * 128 + r) * CKQ + c * 8);
            }
        }
        CP_COMMIT();                        // always: keeps wait_group accounting exact

        // exp (log2 domain), partial row sums, pack + store unnormalized P
        uint32_t* pb = pbase + kt * 8192;
#pragma unroll
        for (int nt = 0; nt < 16; nt++) {
            const float p0 = ex2f(sv[nt][0]);
            const float p1 = ex2f(sv[nt][1]);
            const float p2 = ex2f(sv[nt][2]);
            const float p3 = ex2f(sv[nt][3]);
            rsum0 += p0 + p1;
            rsum1 += p2 + p3;
            pb[(m0 + g) * 64     + nt * 4 + t] = pack_bf2(p0, p1);
            pb[(m0 + g + 8) * 64 + nt * 4 + t] = pack_bf2(p2, p3);
        }
    }

    // quad-reduce partial row sums, lane t==0 writes this half's sums
    rsum0 += __shfl_xor_sync(0xffffffffu, rsum0, 1);
    rsum0 += __shfl_xor_sync(0xffffffffu, rsum0, 2);
    rsum1 += __shfl_xor_sync(0xffffffffu, rsum1, 1);
    rsum1 += __shfl_xor_sync(0xffffffffu, rsum1, 2);
    if (t == 0) {
        g_rsumH[h * (Bsz * NF) + b * NF + q0 + m0 + g]     = rsum0;
        g_rsumH[h * (Bsz * NF) + b * NF + q0 + m0 + g + 8] = rsum1;
    }
}

// ---------------- kernel 3: O = P @ V, scaled by 1/rsum --------------------
// CTA: 128 q x 128 out channels, 256 threads, 8 warps (4M x 2N), M32N64/warp.
// K-step 64, 2-stage cp.async (36.8KB/stage), reg-capped 128 -> 2 CTAs/SM.
#define PV_ST 72                          // halves stride (64 + 8) = 144B rows
#define PV_A_BYTES 18432                  // 128 rows x 144B
#define PV_STAGE (2 * PV_A_BYTES)         // A + B = 36864
#define PV_SMEM (2 * PV_STAGE)            // 73728

__global__ __launch_bounds__(256, 2) void k_pv(float* __restrict__ out) {
    extern __shared__ char smem[];
    const uint32_t sb = smem_u32(smem);
    const int tid = threadIdx.x;
    const int w = tid >> 5, lane = tid & 31;
    const int g = lane >> 2, t = lane & 3;
    const int mw = w & 3, nw = w >> 2;          // 4 x 2 warp grid
    const int mbase = mw * 32, nbase = nw * 64;

    const int b  = blockIdx.x >> 5;
    const int qt = (blockIdx.x >> 1) & 15;
    const int nh = blockIdx.x & 1;
    const int q0 = qt * 128;

    const __nv_bfloat16* gP = &g_P[((size_t)(b * 16 + qt)) * 32 * 16384];
    const __nv_bfloat16* gV = &g_Vt[((size_t)(b * COUT + nh * 128)) * NK];

    // prefetch ks = 0, 1 (each: A = P 128x64 slice, B = Vt 128x64 slice)
#pragma unroll
    for (int pre = 0; pre < 2; pre++) {
        const uint32_t ab = sb + pre * PV_STAGE;
        const uint32_t bb = ab + PV_A_BYTES;
        const int blk = pre >> 1, half = pre & 1;   // pre<2: blk=0, half=pre
        for (int i = tid; i < 2048; i += 256) {
            const int r = (i & 1023) >> 3, c = i & 7;
            if (i < 1024)
                cp16(ab + r * 144 + c * 16,
                     gP + (size_t)blk * 16384 + r * 128 + half * 64 + c * 8);
            else
                cp16(bb + r * 144 + c * 16,
                     gV + (size_t)r * NK + blk * 128 + half * 64 + c * 8);
        }
        CP_COMMIT();
    }

    float acc[2][8][4];
#pragma unroll
    for (int mt = 0; mt < 2; mt++)
#pragma unroll
        for (int nt = 0; nt < 8; nt++) {
            acc[mt][nt][0] = acc[mt][nt][1] = acc[mt][nt][2] = acc[mt][nt][3] = 0.f;
        }

    for (int ks = 0; ks < 64; ks++) {           // 64 K-steps of 64
        const int s = ks & 1;
        const __nv_bfloat16* As_ = reinterpret_cast<const __nv_bfloat16*>(smem + s * PV_STAGE);
        const __nv_bfloat16* Bs_ = As_ + PV_A_BYTES / 2;

        CP_WAIT(1);
        __syncthreads();

#pragma unroll
        for (int kk = 0; kk < 4; kk++) {
            const int k0 = kk * 16;
            unsigned a[2][4];
#pragma unroll
            for (int mt = 0; mt < 2; mt++) {
                const int r0 = mbase + mt * 16 + g;
                a[mt][0] = *reinterpret_cast<const unsigned*>(&As_[r0       * PV_ST + k0 + 2 * t]);
                a[mt][1] = *reinterpret_cast<const unsigned*>(&As_[(r0 + 8) * PV_ST + k0 + 2 * t]);
                a[mt][2] = *reinterpret_cast<const unsigned*>(&As_[r0       * PV_ST + k0 + 8 + 2 * t]);
                a[mt][3] = *reinterpret_cast<const unsigned*>(&As_[(r0 + 8) * PV_ST + k0 + 8 + 2 * t]);
            }
#pragma unroll
            for (int nt = 0; nt < 8; nt++) {
                const int n = nbase + nt * 8 + g;
                unsigned bf[2];
                bf[0] = *reinterpret_cast<const unsigned*>(&Bs_[n * PV_ST + k0 + 2 * t]);
                bf[1] = *reinterpret_cast<const unsigned*>(&Bs_[n * PV_ST + k0 + 8 + 2 * t]);
                mma_bf16(acc[0][nt], a[0], bf);
                mma_bf16(acc[1][nt], a[1], bf);
            }
        }

        __syncthreads();
        if (ks + 2 < 64) {
            const uint32_t ab = sb + s * PV_STAGE;
            const uint32_t bb = ab + PV_A_BYTES;
            const int tn = ks + 2;
            const int blk = tn >> 1, half = tn & 1;
            for (int i = tid; i < 2048; i += 256) {
                const int r = (i & 1023) >> 3, c = i & 7;
                if (i < 1024)
                    cp16(ab + r * 144 + c * 16,
                         gP + (size_t)blk * 16384 + r * 128 + half * 64 + c * 8);
                else
                    cp16(bb + r * 144 + c * 16,
                         gV + (size_t)r * NK + blk * 128 + half * 64 + c * 8);
            }
        }
        CP_COMMIT();
    }

    // epilogue: scale by 1/(rsum half0 + half1), write fp32 output
#pragma unroll
    for (int mt = 0; mt < 2; mt++) {
        const int r = mbase + mt * 16 + g;
        const int ridx = b * NF + q0 + r;
        const float ia = 1.f / (g_rsumH[ridx]     + g_rsumH[Bsz * NF + ridx]);
        const float ib = 1.f / (g_rsumH[ridx + 8] + g_rsumH[Bsz * NF + ridx + 8]);
        const size_t row0 = (size_t)(b * SEQ + q0 + r) * COUT;
        const size_t row1 = (size_t)(b * SEQ + q0 + r + 8) * COUT;
#pragma unroll
        for (int nt = 0; nt < 8; nt++) {
            const int col = nh * 128 + nbase + nt * 8 + 2 * t;
            *reinterpret_cast<float2*>(&out[row0 + col]) =
                make_float2(acc[mt][nt][0] * ia, acc[mt][nt][1] * ia);
            *reinterpret_cast<float2*>(&out[row1 + col]) =
                make_float2(acc[mt][nt][2] * ib, acc[mt][nt][3] * ib);
        }
    }
}

// ---------------- launch ----------------------------------------------------
extern "C" void kernel_launch(void* const* d_in, const int* in_sizes, int n_in,
                              void* d_out, int out_size) {
    const float* feat = (const float*)d_in[0];
    // d_in[1] = keep_flag (unused; layout is deterministic)
    const float* Wq = (const float*)d_in[2];
    const float* bq = (const float*)d_in[3];
    const float* Wk = (const float*)d_in[4];
    const float* bk = (const float*)d_in[5];
    const float* Wv = (const float*)d_in[6];
    const float* bv = (const float*)d_in[7];
    float* out = (float*)d_out;

    cudaFuncSetAttribute(k_proj,  cudaFuncAttributeMaxDynamicSharedMemorySize, PROJ_SMEM);
    cudaFuncSetAttribute(k_score, cudaFuncAttributeMaxDynamicSharedMemorySize, SCORE_SMEM);
    cudaFuncSetAttribute(k_pv,    cudaFuncAttributeMaxDynamicSharedMemorySize, PV_SMEM);

    k_convert<<<320, 256>>>(Wq, Wk, Wv);
    k_proj<<<(Bsz * SEQ) / 256, 256, PROJ_SMEM>>>(feat, bq, bk, bv, out);
    k_score<<<Bsz * 16 * 2, 256, SCORE_SMEM>>>();
    k_pv<<<Bsz * 16 * 2, 256, PV_SMEM>>>(out);
}

// round 14
// speedup vs baseline: 1.2242x; 1.0345x over previous
#include <cuda_runtime.h>
#include <cuda_bf16.h>
#include <cstdint>

#define Bsz  8
#define NF   2048
#define NK   4096
#define CIN  256
#define CKQ  64
#define COUT 256
#define SEQ  (NF + NK)

// ---------------- scratch (__device__ globals; no allocations allowed) -----
__device__ __align__(16) __nv_bfloat16 g_Wq[CKQ * CIN];
__device__ __align__(16) __nv_bfloat16 g_Wkv[(CKQ + COUT) * CIN];
__device__ __align__(16) __nv_bfloat16 g_Q[Bsz * NF * CKQ];        // log2-domain scaled
__device__ __align__(16) __nv_bfloat16 g_K[Bsz * NK * CKQ];
__device__ __align__(16) __nv_bfloat16 g_Vt[Bsz * COUT * NK];      // [b][c][key]
__device__ __align__(16) __nv_bfloat16 g_P[Bsz * NF * NK];         // 128 MB, blocked [b][qt][kt][128x128]
__device__ __align__(16) float         g_rsumH[2 * Bsz * NF];      // per-kt-half row sums

// 1/sqrt(64) * log2(e): scores land directly in log2 domain -> ex2.approx
#define SCALE_Q 0.180336884f

// =================== helpers =============================================
__device__ __forceinline__ uint32_t smem_u32(const void* p) {
    uint32_t a;
    asm("{ .reg .u64 t; cvta.to.shared.u64 t, %1; cvt.u32.u64 %0, t; }" : "=r"(a) : "l"(p));
    return a;
}
__device__ __forceinline__ float ex2f(float x) {
    float y; asm("ex2.approx.ftz.f32 %0, %1;" : "=f"(y) : "f"(x)); return y;
}
__device__ __forceinline__ unsigned pack_bf2(float lo, float hi) {
    __nv_bfloat162 h = __floats2bfloat162_rn(lo, hi);
    return *reinterpret_cast<unsigned*>(&h);
}
__device__ __forceinline__ void cp16(uint32_t dst, const void* src) {
    asm volatile("cp.async.cg.shared.global [%0], [%1], 16;" :: "r"(dst), "l"(src) : "memory");
}
#define CP_COMMIT() asm volatile("cp.async.commit_group;" ::: "memory")
#define CP_WAIT(n)  asm volatile("cp.async.wait_group %0;" :: "n"(n) : "memory")

// ldmatrix x4: four 8x8 b16 tiles; lane groups 0-7/8-15/16-23/24-31 give tile addrs
__device__ __forceinline__ void ldsm_x4(unsigned r[4], uint32_t addr) {
    asm volatile("ldmatrix.sync.aligned.m8n8.x4.shared.b16 {%0,%1,%2,%3}, [%4];"
        : "=r"(r[0]), "=r"(r[1]), "=r"(r[2]), "=r"(r[3]) : "r"(addr));
}

// mma.sync m16n8k16 bf16 -> f32 (sm_80 baseline; family-portable)
__device__ __forceinline__ void mma_bf16(float c[4], const unsigned a[4], const unsigned b0, const unsigned b1) {
    asm volatile(
        "mma.sync.aligned.m16n8k16.row.col.f32.bf16.bf16.f32 "
        "{%0,%1,%2,%3}, {%4,%5,%6,%7}, {%8,%9}, {%0,%1,%2,%3};\n"
        : "+f"(c[0]), "+f"(c[1]), "+f"(c[2]), "+f"(c[3])
        : "r"(a[0]), "r"(a[1]), "r"(a[2]), "r"(a[3]), "r"(b0), "r"(b1));
}
__device__ __forceinline__ void mma_bf16a(float c[4], const unsigned a[4], const unsigned b[2]) {
    mma_bf16(c, a, b[0], b[1]);
}

// ---------------- kernel 0: weight conversion ------------------------------
__global__ void k_convert(const float* __restrict__ Wq, const float* __restrict__ Wk,
                          const float* __restrict__ Wv) {
    int i = blockIdx.x * blockDim.x + threadIdx.x;
    const int n1 = CKQ * CIN;
    const int n2 = (CKQ + COUT) * CIN;
    if (i < n1) g_Wq[i] = __float2bfloat16_rn(Wq[i]);
    if (i < n2) g_Wkv[i] = __float2bfloat16_rn(i < n1 ? Wk[i] : Wv[i - n1]);
}

// ---------------- kernel 1: fused QKV projection + keep-row copy -----------
// 256-row tile per CTA (grid 192), 8 warps x M32. (R13 config, unchanged.)
#define AS_STRIDE 264
#define VS_STRIDE 66
#define PROJ_SMEM (256 * AS_STRIDE * 2 + 256 * VS_STRIDE * 2)   // 168960

__global__ __launch_bounds__(256) void k_proj(const float* __restrict__ feat,
                                              const float* __restrict__ bq,
                                              const float* __restrict__ bk,
                                              const float* __restrict__ bv,
                                              float* __restrict__ out) {
    extern __shared__ char smem[];
    __nv_bfloat16* As  = reinterpret_cast<__nv_bfloat16*>(smem);
    __nv_bfloat16* Vsm = reinterpret_cast<__nv_bfloat16*>(smem + 256 * AS_STRIDE * 2);

    const int tid = threadIdx.x;
    const int w = tid >> 5, lane = tid & 31;
    const int g = lane >> 2, t = lane & 3;
    const int m0 = w * 32;

    const int row0 = blockIdx.x * 256;
    const int b = row0 / SEQ;
    const int pos0 = row0 % SEQ;
    const bool is_fill = pos0 < NF;

    if (!is_fill) {
        const float4* src = reinterpret_cast<const float4*>(feat + (size_t)row0 * CIN);
        float4* dst = reinterpret_cast<float4*>(out + (size_t)row0 * CIN);
        for (int i = tid; i < 256 * CIN / 4; i += 256) dst[i] = src[i];
    }

    for (int i = tid; i < 256 * 64; i += 256) {
        const int r = i >> 6, c4 = i & 63;
        float4 v = *reinterpret_cast<const float4*>(&feat[(size_t)(row0 + r) * CIN + c4 * 4]);
        *reinterpret_cast<__nv_bfloat162*>(&As[r * AS_STRIDE + c4 * 4]) = __floats2bfloat162_rn(v.x, v.y);
        *reinterpret_cast<__nv_bfloat162*>(&As[r * AS_STRIDE + c4 * 4 + 2]) = __floats2bfloat162_rn(v.z, v.w);
    }
    __syncthreads();

    const int nchunks = is_fill ? 1 : 5;
    for (int nc = 0; nc < nchunks; nc++) {
        const __nv_bfloat16* W = is_fill ? g_Wq : g_Wkv;
        const int nbase = is_fill ? 0 : nc * 64;

        float acc[2][8][4];
#pragma unroll
        for (int mt = 0; mt < 2; mt++)
#pragma unroll
            for (int nt = 0; nt < 8; nt++) {
                acc[mt][nt][0] = acc[mt][nt][1] = acc[mt][nt][2] = acc[mt][nt][3] = 0.f;
            }

#pragma unroll
        for (int kt = 0; kt < 16; kt++) {
            const int k0 = kt * 16;
            unsigned a[2][4];
#pragma unroll
            for (int mt = 0; mt < 2; mt++) {
                const int r0 = m0 + mt * 16 + g;
                a[mt][0] = *reinterpret_cast<const unsigned*>(&As[r0       * AS_STRIDE + k0 + 2 * t]);
                a[mt][1] = *reinterpret_cast<const unsigned*>(&As[(r0 + 8) * AS_STRIDE + k0 + 2 * t]);
                a[mt][2] = *reinterpret_cast<const unsigned*>(&As[r0       * AS_STRIDE + k0 + 8 + 2 * t]);
                a[mt][3] = *reinterpret_cast<const unsigned*>(&As[(r0 + 8) * AS_STRIDE + k0 + 8 + 2 * t]);
            }
#pragma unroll
            for (int nt = 0; nt < 8; nt++) {
                const int n = nbase + nt * 8 + g;
                unsigned bf[2];
                bf[0] = *reinterpret_cast<const unsigned*>(&W[n * CIN + k0 + 2 * t]);
                bf[1] = *reinterpret_cast<const unsigned*>(&W[n * CIN + k0 + 8 + 2 * t]);
                mma_bf16a(acc[0][nt], a[0], bf);
                mma_bf16a(acc[1][nt], a[1], bf);
            }
        }

        if (is_fill) {
#pragma unroll
            for (int mt = 0; mt < 2; mt++) {
                const int qrow = b * NF + pos0 + m0 + mt * 16 + g;
#pragma unroll
                for (int nt = 0; nt < 8; nt++) {
                    const int col = nt * 8 + 2 * t;
                    const float b0v = bq[col], b1v = bq[col + 1];
                    *reinterpret_cast<unsigned*>(&g_Q[(size_t)qrow * CKQ + col]) =
                        pack_bf2((acc[mt][nt][0] + b0v) * SCALE_Q, (acc[mt][nt][1] + b1v) * SCALE_Q);
                    *reinterpret_cast<unsigned*>(&g_Q[(size_t)(qrow + 8) * CKQ + col]) =
                        pack_bf2((acc[mt][nt][2] + b0v) * SCALE_Q, (acc[mt][nt][3] + b1v) * SCALE_Q);
                }
            }
        } else if (nc == 0) {
#pragma unroll
            for (int mt = 0; mt < 2; mt++) {
                const int krow = b * NK + (pos0 - NF) + m0 + mt * 16 + g;
#pragma unroll
                for (int nt = 0; nt < 8; nt++) {
                    const int col = nt * 8 + 2 * t;
                    const float b0v = bk[col], b1v = bk[col + 1];
                    *reinterpret_cast<unsigned*>(&g_K[(size_t)krow * CKQ + col]) =
                        pack_bf2(acc[mt][nt][0] + b0v, acc[mt][nt][1] + b1v);
                    *reinterpret_cast<unsigned*>(&g_K[(size_t)(krow + 8) * CKQ + col]) =
                        pack_bf2(acc[mt][nt][2] + b0v, acc[mt][nt][3] + b1v);
                }
            }
        } else {
#pragma unroll
            for (int mt = 0; mt < 2; mt++) {
                const int r0 = m0 + mt * 16 + g;
#pragma unroll
                for (int nt = 0; nt < 8; nt++) {
                    const int col = nt * 8 + 2 * t;
                    const int nglob = (nc - 1) * 64 + col;
                    const float b0v = bv[nglob], b1v = bv[nglob + 1];
                    *reinterpret_cast<unsigned*>(&Vsm[r0       * VS_STRIDE + col]) =
                        pack_bf2(acc[mt][nt][0] + b0v, acc[mt][nt][1] + b1v);
                    *reinterpret_cast<unsigned*>(&Vsm[(r0 + 8) * VS_STRIDE + col]) =
                        pack_bf2(acc[mt][nt][2] + b0v, acc[mt][nt][3] + b1v);
                }
            }
            __syncthreads();
            const int key0 = pos0 - NF;
            for (int i = tid; i < 64 * 128; i += 256) {
                const int n = i >> 7;
                const int kp = i & 127;
                __nv_bfloat162 h;
                h.x = Vsm[(2 * kp)     * VS_STRIDE + n];
                h.y = Vsm[(2 * kp + 1) * VS_STRIDE + n];
                const int nglob = (nc - 1) * 64 + n;
                *reinterpret_cast<__nv_bfloat162*>(
                    &g_Vt[((size_t)(b * COUT + nglob)) * NK + key0 + 2 * kp]) = h;
            }
            __syncthreads();
        }
    }
}

// ---------------- kernel 2: scores + exp -> unnormalized P -----------------
// Each CTA: 128 q rows x HALF the KV range (16 tiles). grid = 256.
// K fragments via ldmatrix.x4. 3-stage cp.async K pipeline. 2 CTAs/SM.
#define SC_QS 72
#define SC_KS 72
#define SC_SMK(s) (18432 + (s) * 18432)
#define SCORE_SMEM (4 * 18432)     // Q + 3 K stages = 73728

__global__ __launch_bounds__(256, 2) void k_score() {
    extern __shared__ char smem[];
    const uint32_t sb = smem_u32(smem);
    const int tid = threadIdx.x;
    const int w = tid >> 5, lane = tid & 31;
    const int g = lane >> 2, t = lane & 3;
    const int m0 = w * 16;
    const int b  = blockIdx.x >> 5;
    const int qt = (blockIdx.x >> 1) & 15;
    const int h  = blockIdx.x & 1;
    const int q0 = qt * 128;
    const int kt0 = h * 16;

    // ldmatrix lane->address pieces (B operand, 16-row group, 16-col K block)
    const int bRow = (lane & 7) + ((lane >> 4) & 1) * 8;   // row within 16-row group
    const int bKh  = ((lane >> 3) & 1) * 8;                // k half (0 or 8)

    const __nv_bfloat16* gK = &g_K[(size_t)(b * NK) * CKQ];

    // stage Q tile
    for (int i = tid; i < 128 * 8; i += 256) {
        const int r = i >> 3, c4 = i & 7;
        const uint4 v = *reinterpret_cast<const uint4*>(
            &g_Q[((size_t)(b * NF + q0 + r)) * CKQ + c4 * 8]);
        *reinterpret_cast<uint4*>(smem + (r * SC_QS + c4 * 8) * 2) = v;
    }

    // prefetch K tiles kt0 .. kt0+2
#pragma unroll
    for (int pre = 0; pre < 3; pre++) {
        const uint32_t kb = sb + SC_SMK(pre);
        for (int i = tid; i < 1024; i += 256) {
            const int r = i >> 3, c = i & 7;
            cp16(kb + (r * SC_KS + c * 8) * 2, gK + (size_t)((kt0 + pre) * 128 + r) * CKQ + c * 8);
        }
        CP_COMMIT();
    }
    __syncthreads();

    const __nv_bfloat16* Qs = reinterpret_cast<const __nv_bfloat16*>(smem);
    unsigned qf[4][4];
#pragma unroll
    for (int j = 0; j < 4; j++) {
        const int k0 = j * 16;
        qf[j][0] = *reinterpret_cast<const unsigned*>(&Qs[(m0 + g)     * SC_QS + k0 + 2 * t]);
        qf[j][1] = *reinterpret_cast<const unsigned*>(&Qs[(m0 + g + 8) * SC_QS + k0 + 2 * t]);
        qf[j][2] = *reinterpret_cast<const unsigned*>(&Qs[(m0 + g)     * SC_QS + k0 + 8 + 2 * t]);
        qf[j][3] = *reinterpret_cast<const unsigned*>(&Qs[(m0 + g + 8) * SC_QS + k0 + 8 + 2 * t]);
    }

    float rsum0 = 0.f, rsum1 = 0.f;
    uint32_t* pbase = reinterpret_cast<uint32_t*>(&g_P[((size_t)(b * 16 + qt)) * 32 * 16384]);

    for (int i = 0; i < 16; i++) {
        const int kt = kt0 + i;
        const int s = i % 3;
        const uint32_t ksb = sb + SC_SMK(s);

        CP_WAIT(2);
        __syncthreads();

        float sv[16][4];
#pragma unroll
        for (int nt = 0; nt < 16; nt++) { sv[nt][0] = sv[nt][1] = sv[nt][2] = sv[nt][3] = 0.f; }
#pragma unroll
        for (int j = 0; j < 4; j++) {
            const int k0 = j * 16;
#pragma unroll
            for (int np = 0; np < 8; np++) {       // 8 pairs of n-tiles
                unsigned bb[4];
                ldsm_x4(bb, ksb + (uint32_t)((np * 16 + bRow) * SC_KS + k0 + bKh) * 2);
                mma_bf16(sv[2 * np],     qf[j], bb[0], bb[1]);
                mma_bf16(sv[2 * np + 1], qf[j], bb[2], bb[3]);
            }
        }

        __syncthreads();                    // done reading stage s
        if (i + 3 < 16) {                   // prefetch tile kt+3 into stage s
            for (int ii = tid; ii < 1024; ii += 256) {
                const int r = ii >> 3, c = ii & 7;
                cp16(ksb + (r * SC_KS + c * 8) * 2, gK + (size_t)((kt + 3) * 128 + r) * CKQ + c * 8);
            }
        }
        CP_COMMIT();                        // always: keeps wait_group accounting exact

        // exp (log2 domain), partial row sums, pack + store unnormalized P
        uint32_t* pb = pbase + kt * 8192;
#pragma unroll
        for (int nt = 0; nt < 16; nt++) {
            const float p0 = ex2f(sv[nt][0]);
            const float p1 = ex2f(sv[nt][1]);
            const float p2 = ex2f(sv[nt][2]);
            const float p3 = ex2f(sv[nt][3]);
            rsum0 += p0 + p1;
            rsum1 += p2 + p3;
            pb[(m0 + g) * 64     + nt * 4 + t] = pack_bf2(p0, p1);
            pb[(m0 + g + 8) * 64 + nt * 4 + t] = pack_bf2(p2, p3);
        }
    }

    // quad-reduce partial row sums, lane t==0 writes this half's sums
    rsum0 += __shfl_xor_sync(0xffffffffu, rsum0, 1);
    rsum0 += __shfl_xor_sync(0xffffffffu, rsum0, 2);
    rsum1 += __shfl_xor_sync(0xffffffffu, rsum1, 1);
    rsum1 += __shfl_xor_sync(0xffffffffu, rsum1, 2);
    if (t == 0) {
        g_rsumH[h * (Bsz * NF) + b * NF + q0 + m0 + g]     = rsum0;
        g_rsumH[h * (Bsz * NF) + b * NF + q0 + m0 + g + 8] = rsum1;
    }
}

// ---------------- kernel 3: O = P @ V, scaled by 1/rsum --------------------
// CTA: 128 q x 128 out channels, 8 warps (4M x 2N), M32N64/warp.
// K-step 64, 3-stage cp.async, ldmatrix fragments, 2 CTAs/SM.
#define PV_ST 72                          // halves stride -> 144B rows
#define PV_A_BYTES 18432                  // 128 rows x 144B
#define PV_STAGE (2 * PV_A_BYTES)         // A + B = 36864
#define PV_SMEM (3 * PV_STAGE)            // 110592

__global__ __launch_bounds__(256, 2) void k_pv(float* __restrict__ out) {
    extern __shared__ char smem[];
    const uint32_t sb = smem_u32(smem);
    const int tid = threadIdx.x;
    const int w = tid >> 5, lane = tid & 31;
    const int g = lane >> 2, t = lane & 3;
    const int mw = w & 3, nw = w >> 2;          // 4 x 2 warp grid
    const int mbase = mw * 32, nbase = nw * 64;

    // ldmatrix lane->address pieces
    const int aRow = lane & 15;                     // A: row within 16-row tile
    const int aKh  = (lane >> 4) * 8;               // A: k half
    const int bRow = (lane & 7) + ((lane >> 4) & 1) * 8;   // B: row within 16-row group
    const int bKh  = ((lane >> 3) & 1) * 8;

    const int b  = blockIdx.x >> 5;
    const int qt = (blockIdx.x >> 1) & 15;
    const int nh = blockIdx.x & 1;
    const int q0 = qt * 128;

    const __nv_bfloat16* gP = &g_P[((size_t)(b * 16 + qt)) * 32 * 16384];
    const __nv_bfloat16* gV = &g_Vt[((size_t)(b * COUT + nh * 128)) * NK];

    // prefetch ks = 0..2 (each: A = P 128x64 slice, B = Vt 128x64 slice)
#pragma unroll
    for (int pre = 0; pre < 3; pre++) {
        const uint32_t ab = sb + pre * PV_STAGE;
        const uint32_t bb = ab + PV_A_BYTES;
        const int blk = pre >> 1, half = pre & 1;
        for (int i = tid; i < 2048; i += 256) {
            const int r = (i & 1023) >> 3, c = i & 7;
            if (i < 1024)
                cp16(ab + r * 144 + c * 16,
                     gP + (size_t)blk * 16384 + r * 128 + half * 64 + c * 8);
            else
                cp16(bb + r * 144 + c * 16,
                     gV + (size_t)r * NK + blk * 128 + half * 64 + c * 8);
        }
        CP_COMMIT();
    }

    float acc[2][8][4];
#pragma unroll
    for (int mt = 0; mt < 2; mt++)
#pragma unroll
        for (int nt = 0; nt < 8; nt++) {
            acc[mt][nt][0] = acc[mt][nt][1] = acc[mt][nt][2] = acc[mt][nt][3] = 0.f;
        }

    for (int ks = 0; ks < 64; ks++) {           // 64 K-steps of 64
        const int s = ks % 3;
        const uint32_t aB = sb + s * PV_STAGE;
        const uint32_t bB = aB + PV_A_BYTES;

        CP_WAIT(2);
        __syncthreads();

#pragma unroll
        for (int kk = 0; kk < 4; kk++) {
            const int k0 = kk * 16;
            unsigned a[2][4];
#pragma unroll
            for (int mt = 0; mt < 2; mt++)
                ldsm_x4(a[mt], aB + (uint32_t)((mbase + mt * 16 + aRow) * PV_ST + k0 + aKh) * 2);
#pragma unroll
            for (int np = 0; np < 4; np++) {      // 4 pairs of n-tiles (64 cols)
                unsigned bb[4];
                ldsm_x4(bb, bB + (uint32_t)((nbase + np * 16 + bRow) * PV_ST + k0 + bKh) * 2);
                mma_bf16(acc[0][2 * np],     a[0], bb[0], bb[1]);
                mma_bf16(acc[1][2 * np],     a[1], bb[0], bb[1]);
                mma_bf16(acc[0][2 * np + 1], a[0], bb[2], bb[3]);
                mma_bf16(acc[1][2 * np + 1], a[1], bb[2], bb[3]);
            }
        }

        __syncthreads();
        if (ks + 3 < 64) {
            const int tn = ks + 3;
            const int blk = tn >> 1, half = tn & 1;
            for (int i = tid; i < 2048; i += 256) {
                const int r = (i & 1023) >> 3, c = i & 7;
                if (i < 1024)
                    cp16(aB + r * 144 + c * 16,
                         gP + (size_t)blk * 16384 + r * 128 + half * 64 + c * 8);
                else
                    cp16(bB + r * 144 + c * 16,
                         gV + (size_t)r * NK + blk * 128 + half * 64 + c * 8);
            }
        }
        CP_COMMIT();
    }

    // epilogue: scale by 1/(rsum half0 + half1), write fp32 output
#pragma unroll
    for (int mt = 0; mt < 2; mt++) {
        const int r = mbase + mt * 16 + g;
        const int ridx = b * NF + q0 + r;
        const float ia = 1.f / (g_rsumH[ridx]     + g_rsumH[Bsz * NF + ridx]);
        const float ib = 1.f / (g_rsumH[ridx + 8] + g_rsumH[Bsz * NF + ridx + 8]);
        const size_t row0 = (size_t)(b * SEQ + q0 + r) * COUT;
        const size_t row1 = (size_t)(b * SEQ + q0 + r + 8) * COUT;
#pragma unroll
        for (int nt = 0; nt < 8; nt++) {
            const int col = nh * 128 + nbase + nt * 8 + 2 * t;
            *reinterpret_cast<float2*>(&out[row0 + col]) =
                make_float2(acc[mt][nt][0] * ia, acc[mt][nt][1] * ia);
            *reinterpret_cast<float2*>(&out[row1 + col]) =
                make_float2(acc[mt][nt][2] * ib, acc[mt][nt][3] * ib);
        }
    }
}

// ---------------- launch ----------------------------------------------------
extern "C" void kernel_launch(void* const* d_in, const int* in_sizes, int n_in,
                              void* d_out, int out_size) {
    const float* feat = (const float*)d_in[0];
    // d_in[1] = keep_flag (unused; layout is deterministic)
    const float* Wq = (const float*)d_in[2];
    const float* bq = (const float*)d_in[3];
    const float* Wk = (const float*)d_in[4];
    const float* bk = (const float*)d_in[5];
    const float* Wv = (const float*)d_in[6];
    const float* bv = (const float*)d_in[7];
    float* out = (float*)d_out;

    cudaFuncSetAttribute(k_proj,  cudaFuncAttributeMaxDynamicSharedMemorySize, PROJ_SMEM);
    cudaFuncSetAttribute(k_score, cudaFuncAttributeMaxDynamicSharedMemorySize, SCORE_SMEM);
    cudaFuncSetAttribute(k_pv,    cudaFuncAttributeMaxDynamicSharedMemorySize, PV_SMEM);

    k_convert<<<320, 256>>>(Wq, Wk, Wv);
    k_proj<<<(Bsz * SEQ) / 256, 256, PROJ_SMEM>>>(feat, bq, bk, bv, out);
    k_score<<<Bsz * 16 * 2, 256, SCORE_SMEM>>>();
    k_pv<<<Bsz * 16 * 2, 256, PV_SMEM>>>(out);
}